// round 3
// baseline (speedup 1.0000x reference)
#include <cuda_runtime.h>
#include <cstdint>

// Problem constants (from reference setup_inputs)
#define MAXB   32
#define MAXN   131072
#define TILE   2048          // points per CTA
#define TPB    256           // threads per CTA
#define PPT    8             // points per thread (TILE / TPB)
#define MAXTILES (MAXN / TILE)   // 64

// Scratch (allocation-free rule: __device__ globals)
__device__ unsigned int g_tile_counts[MAXB * MAXTILES];
__device__ unsigned int g_tile_prefix[MAXB * MAXTILES];
__device__ unsigned int g_batch_total[MAXB];

// Validity: must bit-match the JAX reference. einsum('bnd,bde->bne'):
//   p_e = x*T[0*4+e] + y*T[1*4+e] + z*T[2*4+e] + T[e*4+3]
// Use explicit non-FMA IEEE ops, strict left-to-right.
__device__ __forceinline__ bool is_valid(float x, float y, float z,
                                         float nx, float ny, float nz,
                                         const float* __restrict__ T) {
    float px = __fadd_rn(__fadd_rn(__fadd_rn(__fmul_rn(x, T[0]), __fmul_rn(y, T[4])), __fmul_rn(z, T[8])),  T[3]);
    float py = __fadd_rn(__fadd_rn(__fadd_rn(__fmul_rn(x, T[1]), __fmul_rn(y, T[5])), __fmul_rn(z, T[9])),  T[7]);
    float pz = __fadd_rn(__fadd_rn(__fadd_rn(__fmul_rn(x, T[2]), __fmul_rn(y, T[6])), __fmul_rn(z, T[10])), T[11]);
    float sq = __fadd_rn(__fmul_rn(px, px), __fmul_rn(py, py));
    float ns = __fadd_rn(__fadd_rn(nx, ny), nz);
    return (sq < 1.0f) && (pz < 1.0f) && (ns != 0.0f);
}

// ---------------------------------------------------------------------------
// Kernel 1: per-tile valid counts
// ---------------------------------------------------------------------------
__global__ void __launch_bounds__(TPB) count_kernel(const float* __restrict__ pc,
                                                    const float* __restrict__ tf,
                                                    int N, int tiles) {
    const int b    = blockIdx.y;
    const int tile = blockIdx.x;
    const int tid  = threadIdx.x;
    const float* __restrict__ T = tf + (size_t)b * 16;

    const size_t g0 = (size_t)tile * TILE + (size_t)tid * PPT;   // first point idx in batch
    const float4* __restrict__ src =
        (const float4*)(pc + ((size_t)b * N + g0) * 6);          // 192B-aligned

    unsigned int c = 0;
#pragma unroll
    for (int pp = 0; pp < PPT / 2; pp++) {
        float4 a = src[pp * 3 + 0];
        float4 m = src[pp * 3 + 1];
        float4 e = src[pp * 3 + 2];
        c += is_valid(a.x, a.y, a.z, a.w, m.x, m.y, T) ? 1u : 0u;
        c += is_valid(m.z, m.w, e.x, e.y, e.z, e.w, T) ? 1u : 0u;
    }
    // warp reduce
#pragma unroll
    for (int o = 16; o > 0; o >>= 1) c += __shfl_down_sync(0xFFFFFFFFu, c, o);
    __shared__ unsigned int ws[TPB / 32];
    if ((tid & 31) == 0) ws[tid >> 5] = c;
    __syncthreads();
    if (tid == 0) {
        unsigned int t = 0;
#pragma unroll
        for (int i = 0; i < TPB / 32; i++) t += ws[i];
        g_tile_counts[b * tiles + tile] = t;
    }
}

// ---------------------------------------------------------------------------
// Kernel 2: per-batch exclusive scan over tile counts (tiles <= 64)
// ---------------------------------------------------------------------------
__global__ void scan_kernel(int tiles) {
    const int b   = blockIdx.x;
    const int tid = threadIdx.x;
    __shared__ unsigned int s[MAXTILES];
    unsigned int c = g_tile_counts[b * tiles + tid];
    s[tid] = c;
    __syncthreads();
    for (int off = 1; off < tiles; off <<= 1) {
        unsigned int v   = s[tid];
        unsigned int add = (tid >= off) ? s[tid - off] : 0u;
        __syncthreads();
        s[tid] = v + add;
        __syncthreads();
    }
    g_tile_prefix[b * tiles + tid] = s[tid] - c;   // exclusive
    if (tid == tiles - 1) g_batch_total[b] = s[tid];
}

// ---------------------------------------------------------------------------
// Kernel 3: scatter. Valid point g -> row valid_before(g).
//           Invalid point g -> row K_b + (g - valid_before(g)), value = zeros.
// Every output row written exactly once. Output stores use .cs (evict-first)
// so the 100MB of written lines don't evict the input's L2 residency.
// ---------------------------------------------------------------------------
__global__ void __launch_bounds__(TPB) scatter_kernel(const float* __restrict__ pc,
                                                      const float* __restrict__ tf,
                                                      float* __restrict__ out,
                                                      int N, int tiles) {
    const int b    = blockIdx.y;
    const int tile = blockIdx.x;
    const int tid  = threadIdx.x;
    const int lane = tid & 31;
    const int wid  = tid >> 5;
    const float* __restrict__ T = tf + (size_t)b * 16;

    const size_t g0 = (size_t)tile * TILE + (size_t)tid * PPT;
    const float4* __restrict__ src =
        (const float4*)(pc + ((size_t)b * N + g0) * 6);

    float4 d[PPT / 2 * 3];
    unsigned int mask = 0;
#pragma unroll
    for (int pp = 0; pp < PPT / 2; pp++) {
        float4 a = src[pp * 3 + 0];
        float4 m = src[pp * 3 + 1];
        float4 e = src[pp * 3 + 2];
        d[pp * 3 + 0] = a; d[pp * 3 + 1] = m; d[pp * 3 + 2] = e;
        if (is_valid(a.x, a.y, a.z, a.w, m.x, m.y, T)) mask |= 1u << (pp * 2);
        if (is_valid(m.z, m.w, e.x, e.y, e.z, e.w, T)) mask |= 1u << (pp * 2 + 1);
    }
    unsigned int c = __popc(mask);

    // block exclusive scan of per-thread counts
    unsigned int x = c;
#pragma unroll
    for (int o = 1; o < 32; o <<= 1) {
        unsigned int y = __shfl_up_sync(0xFFFFFFFFu, x, o);
        if (lane >= o) x += y;
    }
    __shared__ unsigned int wsum[TPB / 32];
    if (lane == 31) wsum[wid] = x;
    __syncthreads();
    if (tid == 0) {
        unsigned int run = 0;
#pragma unroll
        for (int i = 0; i < TPB / 32; i++) { unsigned int t = wsum[i]; wsum[i] = run; run += t; }
    }
    __syncthreads();
    const unsigned int thread_excl = wsum[wid] + x - c;   // valid count before this thread in tile

    const unsigned int tilePref = g_tile_prefix[b * tiles + tile];
    const unsigned int Kb       = g_batch_total[b];
    const size_t out_base = (size_t)b * N;

    unsigned int r = 0;   // running valid rank within thread
#pragma unroll
    for (int i = 0; i < PPT; i++) {
        const unsigned int gi = (unsigned int)g0 + i;
        const unsigned int vb = tilePref + thread_excl + r;   // valid_before(gi)
        float2* row;
        if (mask & (1u << i)) {
            row = (float2*)(out + (out_base + vb) * 6);
            const float4 a = d[(i >> 1) * 3 + 0];
            const float4 m = d[(i >> 1) * 3 + 1];
            const float4 e = d[(i >> 1) * 3 + 2];
            float2 v0, v1, v2;
            if ((i & 1) == 0) { v0 = make_float2(a.x, a.y); v1 = make_float2(a.z, a.w); v2 = make_float2(m.x, m.y); }
            else              { v0 = make_float2(m.z, m.w); v1 = make_float2(e.x, e.y); v2 = make_float2(e.z, e.w); }
            __stcs(row + 0, v0); __stcs(row + 1, v1); __stcs(row + 2, v2);
            r++;
        } else {
            const unsigned int dst = Kb + (gi - vb);
            row = (float2*)(out + (out_base + dst) * 6);
            const float2 z = make_float2(0.0f, 0.0f);
            __stcs(row + 0, z); __stcs(row + 1, z); __stcs(row + 2, z);
        }
    }
}

// ---------------------------------------------------------------------------
extern "C" void kernel_launch(void* const* d_in, const int* in_sizes, int n_in,
                              void* d_out, int out_size) {
    const float* pc = (const float*)d_in[0];   // pointclouds (B, N, 6)
    const float* tf = (const float*)d_in[1];   // task_transform (B, 4, 4)

    const int B = in_sizes[1] / 16;
    const int N = (int)((long long)in_sizes[0] / (6LL * B));
    const int tiles = N / TILE;

    dim3 grid(tiles, B);
    count_kernel<<<grid, TPB>>>(pc, tf, N, tiles);
    scan_kernel<<<B, tiles>>>(tiles);
    scatter_kernel<<<grid, TPB>>>(pc, tf, (float*)d_out, N, tiles);
}

// round 4
// speedup vs baseline: 1.5040x; 1.5040x over previous
#include <cuda_runtime.h>
#include <cstdint>

// Problem constants (from reference setup_inputs)
#define MAXB   32
#define MAXN   131072
#define TILE   2048          // points per CTA
#define TPB    256           // threads per CTA
#define PPT    8             // points per thread (TILE / TPB)
#define MAXTILES (MAXN / TILE)   // 64

#define FLAG_AGG (1u << 30)
#define FLAG_PRE (2u << 30)
#define VALMASK  ((1u << 30) - 1u)

// Scratch (allocation-free rule: __device__ globals)
__device__ unsigned int g_status[MAXB * MAXTILES];   // decoupled-lookback state
__device__ unsigned int g_batch_total[MAXB];

// Validity: bit-matches the JAX reference (verified rel_err=0.0 in R3).
// DO NOT change the op order / non-FMA structure.
__device__ __forceinline__ bool is_valid(float x, float y, float z,
                                         float nx, float ny, float nz,
                                         const float* __restrict__ T) {
    float px = __fadd_rn(__fadd_rn(__fadd_rn(__fmul_rn(x, T[0]), __fmul_rn(y, T[4])), __fmul_rn(z, T[8])),  T[3]);
    float py = __fadd_rn(__fadd_rn(__fadd_rn(__fmul_rn(x, T[1]), __fmul_rn(y, T[5])), __fmul_rn(z, T[9])),  T[7]);
    float pz = __fadd_rn(__fadd_rn(__fadd_rn(__fmul_rn(x, T[2]), __fmul_rn(y, T[6])), __fmul_rn(z, T[10])), T[11]);
    float sq = __fadd_rn(__fmul_rn(px, px), __fmul_rn(py, py));
    float ns = __fadd_rn(__fadd_rn(nx, ny), nz);
    return (sq < 1.0f) && (pz < 1.0f) && (ns != 0.0f);
}

// ---------------------------------------------------------------------------
// Kernel 0: reset lookback state (must run every replay — graph-captured)
// ---------------------------------------------------------------------------
__global__ void init_kernel(int n) {
    int i = blockIdx.x * blockDim.x + threadIdx.x;
    if (i < n) g_status[i] = 0u;
}

__device__ __forceinline__ unsigned warp_sum(unsigned v) {
#pragma unroll
    for (int o = 16; o > 0; o >>= 1) v += __shfl_down_sync(0xFFFFFFFFu, v, o);
    return __shfl_sync(0xFFFFFFFFu, v, 0);
}

// ---------------------------------------------------------------------------
// Kernel 1: single-pass compaction with decoupled lookback (per batch).
// Points assigned strided (p = tid + 256*i) so loads are near-coalesced
// (lane stride 24B -> 6 lines per LDG.64 instead of 48 per LDG.128).
// Stable rank within tile = iteration-major, thread-minor order == point order.
// Only VALID rows are written here; the zero tail is written by zero_kernel.
// ---------------------------------------------------------------------------
__global__ void __launch_bounds__(TPB) compact_kernel(const float* __restrict__ pc,
                                                      const float* __restrict__ tf,
                                                      float* __restrict__ out,
                                                      int N, int tiles) {
    const int b    = blockIdx.y;
    const int tile = blockIdx.x;
    const int tid  = threadIdx.x;
    const int lane = tid & 31;
    const int wid  = tid >> 5;
    const float* __restrict__ T = tf + (size_t)b * 16;

    const size_t batch_base = (size_t)b * N;
    const int tile_base = tile * TILE;

    // --- load + classify (strided point assignment) ---
    float2 d[PPT][3];
    unsigned int vbits = 0;
#pragma unroll
    for (int i = 0; i < PPT; i++) {
        const int p = tile_base + tid + i * TPB;
        const float2* __restrict__ q = (const float2*)(pc + (batch_base + p) * 6);
        d[i][0] = q[0]; d[i][1] = q[1]; d[i][2] = q[2];
        bool v = is_valid(d[i][0].x, d[i][0].y, d[i][1].x,
                          d[i][1].y, d[i][2].x, d[i][2].y, T);
        vbits |= (v ? 1u : 0u) << i;
    }

    // --- per-iteration ballots; (iter, warp) count grid ---
    unsigned int ball[PPT];
    __shared__ unsigned int sScan[PPT * (TPB / 32)];   // 64 cells, iter-major
    __shared__ unsigned int sTotal;
    __shared__ unsigned int sExcl;
#pragma unroll
    for (int i = 0; i < PPT; i++) {
        ball[i] = __ballot_sync(0xFFFFFFFFu, (vbits >> i) & 1u);
        if (lane == 0) sScan[i * (TPB / 32) + wid] = __popc(ball[i]);
    }
    __syncthreads();

    // serial exclusive scan of 64 cells (cheap) by thread 0
    if (tid == 0) {
        unsigned int run = 0;
#pragma unroll
        for (int i = 0; i < PPT * (TPB / 32); i++) {
            unsigned int t = sScan[i]; sScan[i] = run; run += t;
        }
        sTotal = run;
    }
    __syncthreads();
    const unsigned int cnt = sTotal;

    // --- publish + warp-parallel lookback (warp 0) ---
    if (wid == 0) {
        unsigned int* st = &g_status[b * tiles + tile];
        if (lane == 0) {
            // flag+count in one word: word-atomicity => no fence needed
            *(volatile unsigned int*)st = (tile == 0 ? FLAG_PRE : FLAG_AGG) | cnt;
        }
        unsigned int running = 0;
        if (tile > 0) {
            int j = tile - 1;
            for (;;) {
                const int idx = j - lane;
                unsigned int s = 0;
                if (idx >= 0) {
                    do { s = *(volatile unsigned int*)&g_status[b * tiles + idx]; }
                    while ((s >> 30) == 0u);
                }
                const unsigned int pmask = __ballot_sync(0xFFFFFFFFu,
                                                         idx >= 0 && (s >> 30) == 2u);
                if (pmask) {
                    const int firstPre = __ffs(pmask) - 1;   // nearest PREFIX
                    unsigned int contrib = (idx >= 0 && lane <= firstPre) ? (s & VALMASK) : 0u;
                    running += warp_sum(contrib);
                    break;
                } else {
                    unsigned int contrib = (idx >= 0) ? (s & VALMASK) : 0u;
                    running += warp_sum(contrib);
                    j -= 32;
                }
            }
        }
        if (lane == 0) {
            sExcl = running;
            if (tile > 0)
                *(volatile unsigned int*)st = FLAG_PRE | (running + cnt);
            if (tile == tiles - 1)
                g_batch_total[b] = running + cnt;
        }
    }
    __syncthreads();
    const unsigned int exclTile = sExcl;
    const unsigned int lmask = (1u << lane) - 1u;

    // --- direct stores of valid rows (compacted region is contiguous) ---
#pragma unroll
    for (int i = 0; i < PPT; i++) {
        if ((vbits >> i) & 1u) {
            const unsigned int rank = sScan[i * (TPB / 32) + wid] + __popc(ball[i] & lmask);
            float2* o = (float2*)(out + (batch_base + exclTile + rank) * 6);
            __stcs(o + 0, d[i][0]);
            __stcs(o + 1, d[i][1]);
            __stcs(o + 2, d[i][2]);
        }
    }
}

// ---------------------------------------------------------------------------
// Kernel 2: zero-fill tail rows [K_b, N) for each batch. Coalesced float2.
// ---------------------------------------------------------------------------
__global__ void __launch_bounds__(TPB) zero_kernel(float* __restrict__ out, int N) {
    const int b    = blockIdx.y;
    const int tile = blockIdx.x;
    const int tid  = threadIdx.x;
    const long long Kf = (long long)g_batch_total[b] * 6;     // first float to zero
    const long long f0 = (long long)tile * TILE * 6;          // CTA float range
    const long long f1 = f0 + (long long)TILE * 6;
    long long lo = Kf > f0 ? Kf : f0;
    if (lo >= f1) return;
    float2* base = (float2*)(out + (size_t)b * N * 6);
    const float2 z = make_float2(0.0f, 0.0f);
    for (long long i = (lo >> 1) + tid; i < (f1 >> 1); i += TPB)
        __stcs(base + i, z);
}

// ---------------------------------------------------------------------------
extern "C" void kernel_launch(void* const* d_in, const int* in_sizes, int n_in,
                              void* d_out, int out_size) {
    const float* pc = (const float*)d_in[0];   // pointclouds (B, N, 6)
    const float* tf = (const float*)d_in[1];   // task_transform (B, 4, 4)

    const int B = in_sizes[1] / 16;
    const int N = (int)((long long)in_sizes[0] / (6LL * B));
    const int tiles = N / TILE;

    init_kernel<<<(B * tiles + 255) / 256, 256>>>(B * tiles);
    dim3 grid(tiles, B);
    compact_kernel<<<grid, TPB>>>(pc, tf, (float*)d_out, N, tiles);
    zero_kernel<<<grid, TPB>>>((float*)d_out, N);
}

// round 6
// speedup vs baseline: 1.6429x; 1.0924x over previous
#include <cuda_runtime.h>
#include <cstdint>

// Problem constants (from reference setup_inputs)
#define MAXB   32
#define MAXN   131072
#define TILE   2048          // points per CTA
#define TPB    256           // threads per CTA
#define PPT    8             // points per thread (TILE / TPB)
#define MAXTILES (MAXN / TILE)   // 64
#define NWARP  (TPB / 32)

#define FLAG_AGG (1u << 30)
#define FLAG_PRE (2u << 30)
#define VALMASK  ((1u << 30) - 1u)

// Tile buffer: TILE*6 floats = 49152 B; + scan cells
#define SMEM_TILE_FLOATS (TILE * 6)
#define SMEM_BYTES (SMEM_TILE_FLOATS * 4 + (PPT * NWARP + 8) * 4)

// Scratch (allocation-free rule: __device__ globals; zero-init at module load)
__device__ unsigned int g_status[MAXB * MAXTILES];   // decoupled-lookback state
__device__ unsigned int g_batch_total[MAXB];

// Validity: bit-matches the JAX reference (verified rel_err=0.0 in R3/R4).
// DO NOT change the op order / non-FMA structure.
__device__ __forceinline__ bool is_valid(float x, float y, float z,
                                         float nx, float ny, float nz,
                                         const float* __restrict__ T) {
    float px = __fadd_rn(__fadd_rn(__fadd_rn(__fmul_rn(x, T[0]), __fmul_rn(y, T[4])), __fmul_rn(z, T[8])),  T[3]);
    float py = __fadd_rn(__fadd_rn(__fadd_rn(__fmul_rn(x, T[1]), __fmul_rn(y, T[5])), __fmul_rn(z, T[9])),  T[7]);
    float pz = __fadd_rn(__fadd_rn(__fadd_rn(__fmul_rn(x, T[2]), __fmul_rn(y, T[6])), __fmul_rn(z, T[10])), T[11]);
    float sq = __fadd_rn(__fmul_rn(px, px), __fmul_rn(py, py));
    float ns = __fadd_rn(__fadd_rn(nx, ny), nz);
    return (sq < 1.0f) && (pz < 1.0f) && (ns != 0.0f);
}

__device__ __forceinline__ unsigned warp_sum(unsigned v) {
#pragma unroll
    for (int o = 16; o > 0; o >>= 1) v += __shfl_down_sync(0xFFFFFFFFu, v, o);
    return __shfl_sync(0xFFFFFFFFu, v, 0);
}

// ---------------------------------------------------------------------------
// Kernel 1: single-pass compaction, decoupled lookback, smem-staged I/O.
//  - tile loaded coalesced (float4) into smem          -> no L1 amplification
//  - classify from smem (strided point assignment)
//  - compacted valid rows staged in smem, stored coalesced (float2)
// Stable rank: point p = tid + i*TPB  ==  rank order (i, tid). Verified R4.
// ---------------------------------------------------------------------------
__global__ void __launch_bounds__(TPB) compact_kernel(const float* __restrict__ pc,
                                                      const float* __restrict__ tf,
                                                      float* __restrict__ out,
                                                      int N, int tiles) {
    extern __shared__ float sTile[];                       // TILE*6 floats
    unsigned int* sScan  = (unsigned int*)(sTile + SMEM_TILE_FLOATS);  // PPT*NWARP
    unsigned int* sMeta  = sScan + PPT * NWARP;            // [0]=total, [1]=excl

    const int b    = blockIdx.y;
    const int tile = blockIdx.x;
    const int tid  = threadIdx.x;
    const int lane = tid & 31;
    const int wid  = tid >> 5;
    const float* __restrict__ T = tf + (size_t)b * 16;

    const size_t batch_base = (size_t)b * N;
    const int tile_base = tile * TILE;

    // --- stage 1: coalesced tile load (global float4 -> smem) ---
    {
        const float4* __restrict__ gsrc =
            (const float4*)(pc + (batch_base + tile_base) * 6);
        float4* s4 = (float4*)sTile;
#pragma unroll
        for (int i = 0; i < SMEM_TILE_FLOATS / 4 / TPB; i++)
            s4[tid + i * TPB] = gsrc[tid + i * TPB];
    }
    __syncthreads();

    // --- stage 2: classify from smem ---
    float2 d[PPT][3];
    unsigned int vbits = 0;
    {
        const float2* s2 = (const float2*)sTile;
#pragma unroll
        for (int i = 0; i < PPT; i++) {
            const int p = tid + i * TPB;                   // local point idx
            d[i][0] = s2[p * 3 + 0];
            d[i][1] = s2[p * 3 + 1];
            d[i][2] = s2[p * 3 + 2];
            bool v = is_valid(d[i][0].x, d[i][0].y, d[i][1].x,
                              d[i][1].y, d[i][2].x, d[i][2].y, T);
            vbits |= (v ? 1u : 0u) << i;
        }
    }

    // --- ballots + (iter, warp) count grid ---
    unsigned int ball[PPT];
#pragma unroll
    for (int i = 0; i < PPT; i++) {
        ball[i] = __ballot_sync(0xFFFFFFFFu, (vbits >> i) & 1u);
        if (lane == 0) sScan[i * NWARP + wid] = __popc(ball[i]);
    }
    __syncthreads();

    if (tid == 0) {
        unsigned int run = 0;
#pragma unroll
        for (int i = 0; i < PPT * NWARP; i++) {
            unsigned int t = sScan[i]; sScan[i] = run; run += t;
        }
        sMeta[0] = run;
    }
    __syncthreads();
    const unsigned int cnt = sMeta[0];
    const unsigned int lmask = (1u << lane) - 1u;

    // --- stage 3a: warp 0 publishes + runs lookback; other warps compact ---
    if (wid == 0) {
        unsigned int* st = &g_status[b * tiles + tile];
        if (lane == 0)
            *(volatile unsigned int*)st = (tile == 0 ? FLAG_PRE : FLAG_AGG) | cnt;
        unsigned int running = 0;
        if (tile > 0) {
            int j = tile - 1;
            for (;;) {
                const int idx = j - lane;
                unsigned int s = 0;
                if (idx >= 0) {
                    do { s = *(volatile unsigned int*)&g_status[b * tiles + idx]; }
                    while ((s >> 30) == 0u);
                }
                const unsigned int pmask = __ballot_sync(0xFFFFFFFFu,
                                                         idx >= 0 && (s >> 30) == 2u);
                if (pmask) {
                    const int firstPre = __ffs(pmask) - 1;
                    unsigned int contrib = (idx >= 0 && lane <= firstPre) ? (s & VALMASK) : 0u;
                    running += warp_sum(contrib);
                    break;
                } else {
                    unsigned int contrib = (idx >= 0) ? (s & VALMASK) : 0u;
                    running += warp_sum(contrib);
                    j -= 32;
                }
            }
        }
        if (lane == 0) {
            sMeta[1] = running;
            if (tile > 0)
                *(volatile unsigned int*)st = FLAG_PRE | (running + cnt);
            if (tile == tiles - 1)
                g_batch_total[b] = running + cnt;
        }
    }

    {
        float2* s2 = (float2*)sTile;                       // reuse tile buffer
#pragma unroll
        for (int i = 0; i < PPT; i++) {
            if ((vbits >> i) & 1u) {
                const unsigned int rank = sScan[i * NWARP + wid] + __popc(ball[i] & lmask);
                s2[rank * 3 + 0] = d[i][0];
                s2[rank * 3 + 1] = d[i][1];
                s2[rank * 3 + 2] = d[i][2];
            }
        }
    }
    __syncthreads();

    // --- stage 3b: coalesced store of the compacted block ---
    const unsigned int exclTile = sMeta[1];
    const unsigned int nF2 = cnt * 3;
    float2* __restrict__ gout = (float2*)(out + (batch_base + exclTile) * 6);
    const float2* s2 = (const float2*)sTile;
    for (unsigned int i = tid; i < nF2; i += TPB)
        __stcs(gout + i, s2[i]);
}

// ---------------------------------------------------------------------------
// Kernel 2: zero-fill tail rows [K_b, N); resets g_status for the next replay.
// Wide path: STG.128 after aligning the head to a float4 boundary.
// ---------------------------------------------------------------------------
__global__ void __launch_bounds__(TPB) zero_kernel(float* __restrict__ out,
                                                   int N, int tiles) {
    const int b    = blockIdx.y;
    const int tile = blockIdx.x;
    const int tid  = threadIdx.x;
    if (tid == 0) g_status[b * tiles + tile] = 0u;         // reset for next replay
    const long long Kf = (long long)g_batch_total[b] * 6;  // first float to zero
    const long long f0 = (long long)tile * TILE * 6;
    const long long f1 = f0 + (long long)TILE * 6;         // multiple of 4
    long long lo = Kf > f0 ? Kf : f0;
    if (lo >= f1) return;
    float* base = out + (size_t)b * N * 6;                 // 16B-aligned
    // head: scalar until float4 alignment (lo -> next multiple of 4)
    const long long lo4 = (lo + 3) & ~3LL;
    if (tid < (int)(lo4 - lo)) base[lo + tid] = 0.0f;
    // body: float4 stores
    float4* b4 = (float4*)base;
    const float4 z4 = make_float4(0.0f, 0.0f, 0.0f, 0.0f);
    for (long long i = (lo4 >> 2) + tid; i < (f1 >> 2); i += TPB)
        __stcs(b4 + i, z4);
}

// ---------------------------------------------------------------------------
extern "C" void kernel_launch(void* const* d_in, const int* in_sizes, int n_in,
                              void* d_out, int out_size) {
    const float* pc = (const float*)d_in[0];   // pointclouds (B, N, 6)
    const float* tf = (const float*)d_in[1];   // task_transform (B, 4, 4)

    const int B = in_sizes[1] / 16;
    const int N = (int)((long long)in_sizes[0] / (6LL * B));
    const int tiles = N / TILE;

    cudaFuncSetAttribute(compact_kernel,
                         cudaFuncAttributeMaxDynamicSharedMemorySize, SMEM_BYTES);

    dim3 grid(tiles, B);
    compact_kernel<<<grid, TPB, SMEM_BYTES>>>(pc, tf, (float*)d_out, N, tiles);
    zero_kernel<<<grid, TPB>>>((float*)d_out, N, tiles);
}